// round 16
// baseline (speedup 1.0000x reference)
#include <cuda_runtime.h>
#include <math.h>

// Problem constants (fixed by the dataset)
#define HH 512
#define WW 512
#define MAXV 2048
#define MAXF 4096
#define VIEW_TAN 0.5773502691896258f   // tan(30 deg)
#define NEARP 0.1f
#define BIGZ 1.0e10f
#define CH 256          // faces per culling chunk (= render block size)
#define NBUK 256        // depth buckets
// fixed conservative bucket range (correctness never depends on it:
// bucket 0 uses lb = -inf, top clamp keeps lb <= zmin by construction)
#define ZRLO 0.3f
#define ZRHI 6.0f
#define TILE_W 16
#define TILE_H 16       // 1 pixel per thread, 256 threads/block
#define NBX (WW / TILE_W)   // 32
#define NBY (HH / TILE_H)   // 32
#define NBLK (NBX * NBY)    // 1024

// ---------------- device scratch (no allocations allowed) ----------------
__device__ float  g_vx[MAXV];
__device__ float  g_vy[MAXV];
__device__ float  g_vz[MAXV];
__device__ float4 g_FA[MAXF];
__device__ float4 g_FB[MAXF];
__device__ float4 g_FC[MAXF];   // {C2, zP, zQ, zR} — z plane coeffs
__device__ float4 g_BB[MAXF];
__device__ float4 g_COL[MAXF];
__device__ float  g_zmin[MAXF];
__device__ int    g_bkt[MAXF];
// bucket-sorted copies
__device__ float4 g_FA2[MAXF];
__device__ float4 g_FB2[MAXF];
__device__ float4 g_FC2[MAXF];
__device__ float4 g_BB2[MAXF];
__device__ int    g_idx2[MAXF];  // original face index
__device__ float  g_zminS[MAXF]; // ACTUAL face zmin per sorted slot
__device__ float  g_lbS[MAXF];   // monotone lower bound per slot
__device__ float  g_partials[NBLK];
__device__ int    g_done;

// =============== kernel 1: vertex transform (one vert / thread) ===========
__global__ __launch_bounds__(256)
void k_verts(const float* __restrict__ v,
             const float* __restrict__ campos,
             const float* __restrict__ camup,
             int nV) {
    __shared__ float sR[9], sEye[3];
    const int tid = threadIdx.x;
    if (tid == 0) {
        float ex = campos[0], ey = campos[1], ez = campos[2];
        float nx = -ex, ny = -ey, nz = -ez;
        float nl = sqrtf(nx*nx + ny*ny + nz*nz) + 1e-12f;
        float zx = nx/nl, zy = ny/nl, zz = nz/nl;
        float ux = camup[0], uy = camup[1], uz = camup[2];
        float ul = sqrtf(ux*ux + uy*uy + uz*uz) + 1e-12f;
        ux /= ul; uy /= ul; uz /= ul;
        float cx = uy*zz - uz*zy;
        float cy = uz*zx - ux*zz;
        float cz = ux*zy - uy*zx;
        float cl = sqrtf(cx*cx + cy*cy + cz*cz) + 1e-12f;
        float xx = cx/cl, xy = cy/cl, xz = cz/cl;
        float yx = zy*xz - zz*xy;
        float yy = zz*xx - zx*xz;
        float yz = zx*xy - zy*xx;
        sR[0]=xx; sR[1]=xy; sR[2]=xz;
        sR[3]=yx; sR[4]=yy; sR[5]=yz;
        sR[6]=zx; sR[7]=zy; sR[8]=zz;
        sEye[0]=ex; sEye[1]=ey; sEye[2]=ez;
        if (blockIdx.x == 0) g_done = 0;   // reset render's reduce counter
    }
    __syncthreads();
    int i = blockIdx.x * 256 + tid;
    if (i >= nV) return;
    float ax = v[3*i+0] - sEye[0];
    float ay = v[3*i+1] - sEye[1];
    float az = v[3*i+2] - sEye[2];
    float cxx = sR[0]*ax + sR[1]*ay + sR[2]*az;
    float cyy = sR[3]*ax + sR[4]*ay + sR[5]*az;
    float czz = sR[6]*ax + sR[7]*ay + sR[8]*az;
    float d = czz * VIEW_TAN + 1e-12f;
    g_vx[i] = cxx / d;
    g_vy[i] = cyy / d;
    g_vz[i] = czz;
}

// =============== kernel 2: per-face setup (verts via L2) ==================
__global__ __launch_bounds__(256)
void k_faces(const int* __restrict__ faces,
             const float* __restrict__ tex,
             int nF) {
    int f = blockIdx.x * 256 + threadIdx.x;
    if (f >= nF) return;

    int i0 = faces[3*f+0], i1 = faces[3*f+1], i2 = faces[3*f+2];
    float p0x = g_vx[i0], p0y = g_vy[i0], z0 = g_vz[i0];
    float p1x = g_vx[i1], p1y = g_vy[i1], z1 = g_vz[i1];
    float p2x = g_vx[i2], p2y = g_vy[i2], z2 = g_vz[i2];

    float area = (p1x-p0x)*(p2y-p0y) - (p1y-p0y)*(p2x-p0x);
    float zmn = fminf(z0, fminf(z1, z2));
    float zmx = fmaxf(z0, fmaxf(z1, z2));

    float4 FA, FB, FC, BB;
    bool live = (fabsf(area) > 1e-8f) && (zmx > NEARP);
    if (live) {
        float s   = (area > 0.0f) ? 1.0f : -1.0f;
        float inv = 1.0f / fabsf(area);
        float e0x = (p2x-p1x)*s, e0y = (p2y-p1y)*s;
        float A0 = -e0y, B0 = e0x, C0 = e0y*p1x - e0x*p1y;
        float e1x = (p0x-p2x)*s, e1y = (p0y-p2y)*s;
        float A1 = -e1y, B1 = e1x, C1 = e1y*p2x - e1x*p2y;
        float e2x = (p1x-p0x)*s, e2y = (p1y-p0y)*s;
        float A2 = -e2y, B2 = e2x, C2 = e2y*p0x - e2x*p0y;
        // z is affine in (px,py): z = zP*px + zQ*py + zR
        float z0i = z0*inv, z1i = z1*inv, z2i = z2*inv;
        float zP = A0*z0i + A1*z1i + A2*z2i;
        float zQ = B0*z0i + B1*z1i + B2*z2i;
        float zR = C0*z0i + C1*z1i + C2*z2i;
        FA = make_float4(A0, B0, C0, A1);
        FB = make_float4(B1, C1, A2, B2);
        FC = make_float4(C2, zP, zQ, zR);
        BB = make_float4(fminf(p0x, fminf(p1x, p2x)),
                         fminf(p0y, fminf(p1y, p2y)),
                         fmaxf(p0x, fmaxf(p1x, p2x)),
                         fmaxf(p0y, fmaxf(p1y, p2y)));
    } else {
        FA = make_float4(0.f, 0.f, -1.f, 0.f);
        FB = make_float4(0.f, -1.f, 0.f, 0.f);
        FC = make_float4(-1.f, 0.f, 0.f, 0.f);
        BB = make_float4(2e9f, 2e9f, -2e9f, -2e9f);
        zmn = 3e38f;
    }
    g_FA[f] = FA; g_FB[f] = FB; g_FC[f] = FC; g_BB[f] = BB;
    g_zmin[f] = zmn;

    int b;
    if (live) {
        const float invw = (float)NBUK / (ZRHI - ZRLO);
        b = (int)((zmn - ZRLO) * invw);
        b = max(0, min(NBUK - 1, b));
    } else {
        b = NBUK;
    }
    g_bkt[f] = b;

    // color: mean of 24 floats, loaded as 6 x float4 (16B aligned: f*96 bytes)
    const float4* t4 = (const float4*)(tex + (size_t)f * 24);
    float4 q0 = t4[0], q1 = t4[1], q2 = t4[2], q3 = t4[3], q4 = t4[4], q5 = t4[5];
    float r  = q0.x + q0.w + q1.z + q2.y + q3.x + q3.w + q4.z + q5.y;
    float g  = q0.y + q1.x + q1.w + q2.z + q3.y + q4.x + q4.w + q5.z;
    float bl = q0.z + q1.y + q2.x + q2.w + q3.z + q4.y + q5.x + q5.w;
    g_COL[f] = make_float4(r*0.125f, g*0.125f, bl*0.125f, 0.f);
}

// ======= kernel 3: bucket scatter (4 blocks x 1024; shared-atomic rank) ====
__global__ __launch_bounds__(1024)
void k_scatter(int nF) {
    __shared__ int sHist[NBUK + 1];   // total per-bucket counts
    __shared__ int sBase[NBUK + 1];   // counts before this slice (then rank ctr)
    __shared__ int sOffE[NBUK + 2];   // exclusive scan of totals

    const int tid = threadIdx.x;
    const int sliceStart = blockIdx.x * 1024;

    for (int i = tid; i <= NBUK; i += 1024) { sHist[i] = 0; sBase[i] = 0; }
    __syncthreads();

    for (int i = tid; i < nF; i += 1024) {
        int b = g_bkt[i];
        atomicAdd(&sHist[b], 1);
        if (i < sliceStart) atomicAdd(&sBase[b], 1);
    }
    __syncthreads();

    // exclusive scan of sHist by warp 0
    if (tid < 32) {
        int acc = 0;
        for (int base = 0; base <= NBUK; base += 32) {
            int i = base + tid;
            int vv = (i <= NBUK) ? sHist[i] : 0;
            int sc = vv;
            #pragma unroll
            for (int d = 1; d < 32; d <<= 1) {
                int n = __shfl_up_sync(0xffffffffu, sc, d);
                if (tid >= d) sc += n;
            }
            if (i <= NBUK) sOffE[i + 1] = acc + sc;
            acc += __shfl_sync(0xffffffffu, sc, 31);
        }
        if (tid == 0) sOffE[0] = 0;
    }
    __syncthreads();

    int f = sliceStart + tid;
    if (f >= nF) return;
    int myb = g_bkt[f];
    // rank = before-slice count + within-slice atomic rank (bucket order
    // arbitrary; image is order-invariant: strict z compares + index tie-break)
    int rank = atomicAdd(&sBase[myb], 1);
    int pos = sOffE[myb] + rank;
    g_FA2[pos] = g_FA[f];
    g_FB2[pos] = g_FB[f];
    g_FC2[pos] = g_FC[f];
    g_BB2[pos] = g_BB[f];
    g_idx2[pos] = f;
    g_zminS[pos] = g_zmin[f];
    float lb;
    if (myb >= NBUK) {
        lb = 3e38f;                 // dead faces: always breakable past
    } else if (myb == 0) {
        lb = -3.3e38f;              // never break inside the first bucket
    } else {
        lb = ZRLO + (float)myb * ((ZRHI - ZRLO) * (1.0f / NBUK)) - 1e-5f;
    }
    g_lbS[pos] = lb;
}

// ====== kernel 4: cull + front-to-back rasterize + loss + final reduce =====
// block = (16,16) = 256 threads, tile = 16x16 px, 1 px/thread
__global__ __launch_bounds__(256)
void k_render(const float* __restrict__ image_ref, int nF,
              float* __restrict__ out) {
    __shared__ float4 sA[CH];
    __shared__ float4 sB[CH];
    __shared__ float4 sC[CH];
    __shared__ float  sLb[CH];
    __shared__ int    sIdx[CH];
    __shared__ int    sWcnt[8];
    __shared__ float  sWmax[8];
    __shared__ float  sRed[256];
    __shared__ int    sIsLast;

    const int tx = threadIdx.x, ty = threadIdx.y;
    const int tid = ty * 16 + tx;
    const int wid = tid >> 5;
    const int lane = tid & 31;
    const int x = blockIdx.x * TILE_W + tx;
    const int y = blockIdx.y * TILE_H + ty;
    const int bid = blockIdx.y * gridDim.x + blockIdx.x;

    const float px = (x + 0.5f) * (2.0f / WW) - 1.0f;
    const float py = 1.0f - (y + 0.5f) * (2.0f / HH);

    const float txmin = (blockIdx.x * TILE_W + 0.5f) * (2.0f / WW) - 1.0f;
    const float txmax = (blockIdx.x * TILE_W + TILE_W - 0.5f) * (2.0f / WW) - 1.0f;
    const float tymax = 1.0f - (blockIdx.y * TILE_H + 0.5f) * (2.0f / HH);
    const float tymin = 1.0f - (blockIdx.y * TILE_H + TILE_H - 0.5f) * (2.0f / HH);
    const float tcx = 0.5f * (txmin + txmax);
    const float tcy = 0.5f * (tymin + tymax);
    const float thx = 0.5f * (txmax - txmin);
    const float thy = 0.5f * (tymax - tymin);

    float zb0 = BIGZ;
    int   b0  = -1;

    if (tid < 8) sWmax[tid] = BIGZ;

    for (int base = 0; base < nF; base += CH) {
        // (1) make last chunk's sWmax visible; smem reusable
        __syncthreads();
        float bm = fmaxf(fmaxf(fmaxf(sWmax[0], sWmax[1]),
                               fmaxf(sWmax[2], sWmax[3])),
                         fmaxf(fmaxf(sWmax[4], sWmax[5]),
                               fmaxf(sWmax[6], sWmax[7])));
        if (g_lbS[base] > bm) break;   // monotone: nothing later can win

        // --- cull (order-preserving ballot compaction) ---
        int f = base + tid;
        bool ok = false;
        float4 fa, fb, fc;
        float lb; int fi;
        if (f < nF) {
            float4 bb = g_BB2[f];
            float zmn = g_zminS[f];
            if ((bb.x <= txmax) && (bb.z >= txmin) &&
                (bb.y <= tymax) && (bb.w >= tymin) &&
                (zmn <= bm)) {
                fa = g_FA2[f];
                fb = g_FB2[f];
                fc = g_FC2[f];
                float u0c = fmaf(fa.x, tcx, fmaf(fa.y, tcy, fa.z));
                float m0  = fmaf(fabsf(fa.x), thx, fmaf(fabsf(fa.y), thy, u0c));
                float u1c = fmaf(fa.w, tcx, fmaf(fb.x, tcy, fb.y));
                float m1  = fmaf(fabsf(fa.w), thx, fmaf(fabsf(fb.x), thy, u1c));
                float u2c = fmaf(fb.z, tcx, fmaf(fb.w, tcy, fc.x));
                float m2  = fmaf(fabsf(fb.z), thx, fmaf(fabsf(fb.w), thy, u2c));
                ok = (m0 >= -1e-5f * fmaxf(1.0f, fabsf(u0c))) &&
                     (m1 >= -1e-5f * fmaxf(1.0f, fabsf(u1c))) &&
                     (m2 >= -1e-5f * fmaxf(1.0f, fabsf(u2c)));
                if (ok) { lb = g_lbS[f]; fi = g_idx2[f]; }
            }
        }
        unsigned mb = __ballot_sync(0xffffffffu, ok);
        if (lane == 0) sWcnt[wid] = __popc(mb);
        __syncthreads();   // (2)
        int cnt = 0, wbase = 0;
        #pragma unroll
        for (int k = 0; k < 8; k++) {
            int c = sWcnt[k];
            cnt += c;
            wbase += (k < wid) ? c : 0;
        }
        if (ok) {
            int p = wbase + __popc(mb & ((1u << lane) - 1u));
            sA[p] = fa; sB[p] = fb; sC[p] = fc;
            sLb[p] = lb; sIdx[p] = fi;
        }
        __syncthreads();   // (3)

        // --- eval (front-to-back; lb monotone within chunk) ---
        float w = zb0;
        #pragma unroll
        for (int off = 16; off > 0; off >>= 1)
            w = fmaxf(w, __shfl_xor_sync(0xffffffffu, w, off));

        for (int i = 0; i < cnt; i++) {
            if (sLb[i] > w) break;     // rest of chunk strictly loses
            if ((i & 63) == 63) {
                float wr = zb0;
                #pragma unroll
                for (int off = 16; off > 0; off >>= 1)
                    wr = fmaxf(wr, __shfl_xor_sync(0xffffffffu, wr, off));
                w = wr;
            }
            float4 fa2 = sA[i];
            float4 fb2 = sB[i];
            float4 fc2 = sC[i];
            int    fi2 = sIdx[i];
            float u0 = fmaf(fa2.x, px, fmaf(fa2.y, py, fa2.z));
            float u1 = fmaf(fa2.w, px, fmaf(fb2.x, py, fb2.y));
            float u2 = fmaf(fb2.z, px, fmaf(fb2.w, py, fc2.x));
            float z  = fmaf(fc2.y, px, fmaf(fc2.z, py, fc2.w));
            float mm = fminf(u0, fminf(u1, u2));
            if (mm >= 0.0f && z > NEARP &&
                (z < zb0 || (z == zb0 && fi2 < b0))) {
                zb0 = z; b0 = fi2;
            }
        }

        // publish per-warp zmax (consumed after next loop-top sync)
        float m = zb0;
        #pragma unroll
        for (int off = 16; off > 0; off >>= 1)
            m = fmaxf(m, __shfl_xor_sync(0xffffffffu, m, off));
        if (lane == 0) sWmax[wid] = m;
    }

    float loss;
    {
        float r = 0.f, g = 0.f, b = 0.f;
        if (b0 >= 0) { float4 c = g_COL[b0]; r = c.x; g = c.y; b = c.z; }
        int ry = HH - 1 - y;
        float d0 = r - image_ref[0*HH*WW + ry*WW + x];
        float d1 = g - image_ref[1*HH*WW + ry*WW + x];
        float d2 = b - image_ref[2*HH*WW + ry*WW + x];
        loss = d0*d0 + d1*d1 + d2*d2;
    }

    __syncthreads();
    sRed[tid] = loss;
    __syncthreads();
    #pragma unroll
    for (int s = 128; s > 0; s >>= 1) {
        if (tid < s) sRed[tid] += sRed[tid + s];
        __syncthreads();
    }
    if (tid == 0) {
        g_partials[bid] = sRed[0];
        __threadfence();
        int prev = atomicAdd(&g_done, 1);
        sIsLast = (prev == NBLK - 1) ? 1 : 0;
    }
    __syncthreads();

    if (sIsLast) {
        volatile float* vp = (volatile float*)g_partials;
        float s = 0.f;
        #pragma unroll
        for (int k = 0; k < NBLK / 256; k++) s += vp[tid + k * 256];
        sRed[tid] = s;
        __syncthreads();
        #pragma unroll
        for (int st = 128; st > 0; st >>= 1) {
            if (tid < st) sRed[tid] += sRed[tid + st];
            __syncthreads();
        }
        if (tid == 0) out[0] = sRed[0];
    }
}

// ---------------- entry point ----------------
extern "C" void kernel_launch(void* const* d_in, const int* in_sizes, int n_in,
                              void* d_out, int out_size) {
    const float* v         = (const float*)d_in[0];   // (1, V, 3)
    const int*   faces     = (const int*)  d_in[1];   // (1, F, 3)
    const float* tex       = (const float*)d_in[2];   // (1, F, 2,2,2,3)
    const float* campos    = (const float*)d_in[3];   // (3,)
    const float* camup     = (const float*)d_in[4];   // (3,)
    const float* image_ref = (const float*)d_in[5];   // (1, 3, H, W)

    int nV = in_sizes[0] / 3;
    int nF = in_sizes[1] / 3;

    k_verts<<<(nV + 255) / 256, 256>>>(v, campos, camup, nV);
    k_faces<<<(nF + 255) / 256, 256>>>(faces, tex, nF);
    k_scatter<<<(nF + 1023) / 1024, 1024>>>(nF);
    k_render<<<dim3(NBX, NBY), dim3(16, 16)>>>(image_ref, nF, (float*)d_out);
}

// round 17
// speedup vs baseline: 1.4666x; 1.4666x over previous
#include <cuda_runtime.h>
#include <math.h>

// Problem constants (fixed by the dataset)
#define HH 512
#define WW 512
#define MAXV 2048
#define MAXF 4096
#define VIEW_TAN 0.5773502691896258f   // tan(30 deg)
#define NEARP 0.1f
#define BIGZ 1.0e10f
#define CH 256          // faces per culling chunk (= render block size)
#define NBUK 256        // depth buckets
// fixed conservative bucket range (correctness never depends on it:
// bucket 0 uses lb = -inf, top clamp keeps lb <= zmin by construction)
#define ZRLO 0.3f
#define ZRHI 6.0f
#define TILE_W 16
#define TILE_H 16       // 1 pixel per thread, 256 threads/block
#define NBX (WW / TILE_W)   // 32
#define NBY (HH / TILE_H)   // 32
#define NBLK (NBX * NBY)    // 1024

// ---------------- device scratch (no allocations allowed) ----------------
__device__ float  g_vx[MAXV];
__device__ float  g_vy[MAXV];
__device__ float  g_vz[MAXV];
__device__ float4 g_FA[MAXF];
__device__ float4 g_FB[MAXF];
__device__ float4 g_FC[MAXF];   // {C2, zP, zQ, zR} — z plane coeffs
__device__ float4 g_BB[MAXF];
__device__ float4 g_COL[MAXF];
__device__ float  g_zmin[MAXF];
__device__ int    g_bkt[MAXF];
// bucket-sorted copies
__device__ float4 g_FA2[MAXF];
__device__ float4 g_FB2[MAXF];
__device__ float4 g_FC2[MAXF];
__device__ float4 g_BB2[MAXF];
__device__ int    g_idx2[MAXF];  // original face index
__device__ float  g_zminS[MAXF]; // ACTUAL face zmin per sorted slot
__device__ float  g_lbS[MAXF];   // monotone lower bound per slot
__device__ float  g_partials[NBLK];
__device__ int    g_done;

// =============== kernel 1: vertex transform (one vert / thread) ===========
__global__ __launch_bounds__(256)
void k_verts(const float* __restrict__ v,
             const float* __restrict__ campos,
             const float* __restrict__ camup,
             int nV) {
    __shared__ float sR[9], sEye[3];
    const int tid = threadIdx.x;
    if (tid == 0) {
        float ex = campos[0], ey = campos[1], ez = campos[2];
        float nx = -ex, ny = -ey, nz = -ez;
        float nl = sqrtf(nx*nx + ny*ny + nz*nz) + 1e-12f;
        float zx = nx/nl, zy = ny/nl, zz = nz/nl;
        float ux = camup[0], uy = camup[1], uz = camup[2];
        float ul = sqrtf(ux*ux + uy*uy + uz*uz) + 1e-12f;
        ux /= ul; uy /= ul; uz /= ul;
        float cx = uy*zz - uz*zy;
        float cy = uz*zx - ux*zz;
        float cz = ux*zy - uy*zx;
        float cl = sqrtf(cx*cx + cy*cy + cz*cz) + 1e-12f;
        float xx = cx/cl, xy = cy/cl, xz = cz/cl;
        float yx = zy*xz - zz*xy;
        float yy = zz*xx - zx*xz;
        float yz = zx*xy - zy*xx;
        sR[0]=xx; sR[1]=xy; sR[2]=xz;
        sR[3]=yx; sR[4]=yy; sR[5]=yz;
        sR[6]=zx; sR[7]=zy; sR[8]=zz;
        sEye[0]=ex; sEye[1]=ey; sEye[2]=ez;
        if (blockIdx.x == 0) g_done = 0;   // reset render's reduce counter
    }
    __syncthreads();
    int i = blockIdx.x * 256 + tid;
    if (i >= nV) return;
    float ax = v[3*i+0] - sEye[0];
    float ay = v[3*i+1] - sEye[1];
    float az = v[3*i+2] - sEye[2];
    float cxx = sR[0]*ax + sR[1]*ay + sR[2]*az;
    float cyy = sR[3]*ax + sR[4]*ay + sR[5]*az;
    float czz = sR[6]*ax + sR[7]*ay + sR[8]*az;
    float d = czz * VIEW_TAN + 1e-12f;
    g_vx[i] = cxx / d;
    g_vy[i] = cyy / d;
    g_vz[i] = czz;
}

// =============== kernel 2: per-face setup (verts via L2) ==================
__global__ __launch_bounds__(256)
void k_faces(const int* __restrict__ faces,
             const float* __restrict__ tex,
             int nF) {
    int f = blockIdx.x * 256 + threadIdx.x;
    if (f >= nF) return;

    int i0 = faces[3*f+0], i1 = faces[3*f+1], i2 = faces[3*f+2];
    float p0x = g_vx[i0], p0y = g_vy[i0], z0 = g_vz[i0];
    float p1x = g_vx[i1], p1y = g_vy[i1], z1 = g_vz[i1];
    float p2x = g_vx[i2], p2y = g_vy[i2], z2 = g_vz[i2];

    float area = (p1x-p0x)*(p2y-p0y) - (p1y-p0y)*(p2x-p0x);
    float zmn = fminf(z0, fminf(z1, z2));
    float zmx = fmaxf(z0, fmaxf(z1, z2));

    float4 FA, FB, FC, BB;
    bool live = (fabsf(area) > 1e-8f) && (zmx > NEARP);
    if (live) {
        float s   = (area > 0.0f) ? 1.0f : -1.0f;
        float inv = 1.0f / fabsf(area);
        float e0x = (p2x-p1x)*s, e0y = (p2y-p1y)*s;
        float A0 = -e0y, B0 = e0x, C0 = e0y*p1x - e0x*p1y;
        float e1x = (p0x-p2x)*s, e1y = (p0y-p2y)*s;
        float A1 = -e1y, B1 = e1x, C1 = e1y*p2x - e1x*p2y;
        float e2x = (p1x-p0x)*s, e2y = (p1y-p0y)*s;
        float A2 = -e2y, B2 = e2x, C2 = e2y*p0x - e2x*p0y;
        // z is affine in (px,py): z = zP*px + zQ*py + zR
        float z0i = z0*inv, z1i = z1*inv, z2i = z2*inv;
        float zP = A0*z0i + A1*z1i + A2*z2i;
        float zQ = B0*z0i + B1*z1i + B2*z2i;
        float zR = C0*z0i + C1*z1i + C2*z2i;
        FA = make_float4(A0, B0, C0, A1);
        FB = make_float4(B1, C1, A2, B2);
        FC = make_float4(C2, zP, zQ, zR);
        BB = make_float4(fminf(p0x, fminf(p1x, p2x)),
                         fminf(p0y, fminf(p1y, p2y)),
                         fmaxf(p0x, fmaxf(p1x, p2x)),
                         fmaxf(p0y, fmaxf(p1y, p2y)));
    } else {
        FA = make_float4(0.f, 0.f, -1.f, 0.f);
        FB = make_float4(0.f, -1.f, 0.f, 0.f);
        FC = make_float4(-1.f, 0.f, 0.f, 0.f);
        BB = make_float4(2e9f, 2e9f, -2e9f, -2e9f);
        zmn = 3e38f;
    }
    g_FA[f] = FA; g_FB[f] = FB; g_FC[f] = FC; g_BB[f] = BB;
    g_zmin[f] = zmn;

    int b;
    if (live) {
        const float invw = (float)NBUK / (ZRHI - ZRLO);
        b = (int)((zmn - ZRLO) * invw);
        b = max(0, min(NBUK - 1, b));
    } else {
        b = NBUK;
    }
    g_bkt[f] = b;

    // color: mean of 24 floats, loaded as 6 x float4 (16B aligned: f*96 bytes)
    const float4* t4 = (const float4*)(tex + (size_t)f * 24);
    float4 q0 = t4[0], q1 = t4[1], q2 = t4[2], q3 = t4[3], q4 = t4[4], q5 = t4[5];
    float r  = q0.x + q0.w + q1.z + q2.y + q3.x + q3.w + q4.z + q5.y;
    float g  = q0.y + q1.x + q1.w + q2.z + q3.y + q4.x + q4.w + q5.z;
    float bl = q0.z + q1.y + q2.x + q2.w + q3.z + q4.y + q5.x + q5.w;
    g_COL[f] = make_float4(r*0.125f, g*0.125f, bl*0.125f, 0.f);
}

// ======= kernel 3: bucket scatter (4 blocks x 1024; shared-atomic rank) ====
__global__ __launch_bounds__(1024)
void k_scatter(int nF) {
    __shared__ int sHist[NBUK + 1];   // total per-bucket counts
    __shared__ int sBase[NBUK + 1];   // counts before this slice (then rank ctr)
    __shared__ int sOffE[NBUK + 2];   // exclusive scan of totals

    const int tid = threadIdx.x;
    const int sliceStart = blockIdx.x * 1024;

    for (int i = tid; i <= NBUK; i += 1024) { sHist[i] = 0; sBase[i] = 0; }
    __syncthreads();

    for (int i = tid; i < nF; i += 1024) {
        int b = g_bkt[i];
        atomicAdd(&sHist[b], 1);
        if (i < sliceStart) atomicAdd(&sBase[b], 1);
    }
    __syncthreads();

    // exclusive scan of sHist by warp 0
    if (tid < 32) {
        int acc = 0;
        for (int base = 0; base <= NBUK; base += 32) {
            int i = base + tid;
            int vv = (i <= NBUK) ? sHist[i] : 0;
            int sc = vv;
            #pragma unroll
            for (int d = 1; d < 32; d <<= 1) {
                int n = __shfl_up_sync(0xffffffffu, sc, d);
                if (tid >= d) sc += n;
            }
            if (i <= NBUK) sOffE[i + 1] = acc + sc;
            acc += __shfl_sync(0xffffffffu, sc, 31);
        }
        if (tid == 0) sOffE[0] = 0;
    }
    __syncthreads();

    int f = sliceStart + tid;
    if (f >= nF) return;
    int myb = g_bkt[f];
    // rank = before-slice count + within-slice atomic rank (bucket order
    // arbitrary; image is order-invariant: strict z compares + index tie-break)
    int rank = atomicAdd(&sBase[myb], 1);
    int pos = sOffE[myb] + rank;
    g_FA2[pos] = g_FA[f];
    g_FB2[pos] = g_FB[f];
    g_FC2[pos] = g_FC[f];
    g_BB2[pos] = g_BB[f];
    g_idx2[pos] = f;
    g_zminS[pos] = g_zmin[f];
    float lb;
    if (myb >= NBUK) {
        lb = 3e38f;                 // dead faces: always breakable past
    } else if (myb == 0) {
        lb = -3.3e38f;              // never break inside the first bucket
    } else {
        lb = ZRLO + (float)myb * ((ZRHI - ZRLO) * (1.0f / NBUK)) - 1e-5f;
    }
    g_lbS[pos] = lb;
}

// ====== kernel 4: cull + front-to-back rasterize + loss + final reduce =====
// block = (16,16) = 256 threads, tile = 16x16 px, 1 px/thread
__global__ __launch_bounds__(256)
void k_render(const float* __restrict__ image_ref, int nF,
              float* __restrict__ out) {
    __shared__ float4 sA[CH];
    __shared__ float4 sB[CH];
    __shared__ float4 sC[CH];
    __shared__ float  sZm[CH];
    __shared__ int    sIdx[CH];
    __shared__ int    sCnt;
    __shared__ float  sWmax[8];
    __shared__ float  sBmax;
    __shared__ float  sRed[256];
    __shared__ int    sIsLast;

    const int tx = threadIdx.x, ty = threadIdx.y;
    const int tid = ty * 16 + tx;
    const int wid = tid >> 5;
    const int x = blockIdx.x * TILE_W + tx;
    const int y = blockIdx.y * TILE_H + ty;
    const int bid = blockIdx.y * gridDim.x + blockIdx.x;

    const float px = (x + 0.5f) * (2.0f / WW) - 1.0f;
    const float py = 1.0f - (y + 0.5f) * (2.0f / HH);

    const float txmin = (blockIdx.x * TILE_W + 0.5f) * (2.0f / WW) - 1.0f;
    const float txmax = (blockIdx.x * TILE_W + TILE_W - 0.5f) * (2.0f / WW) - 1.0f;
    const float tymax = 1.0f - (blockIdx.y * TILE_H + 0.5f) * (2.0f / HH);
    const float tymin = 1.0f - (blockIdx.y * TILE_H + TILE_H - 0.5f) * (2.0f / HH);
    const float tcx = 0.5f * (txmin + txmax);
    const float tcy = 0.5f * (tymin + tymax);
    const float thx = 0.5f * (txmax - txmin);
    const float thy = 0.5f * (tymax - tymin);

    float zb0 = BIGZ;
    int   b0  = -1;

    if (tid == 0) sBmax = BIGZ;
    __syncthreads();

    for (int base = 0; base < nF; base += CH) {
        float zCap = sBmax;
        if (g_lbS[base] > zCap) break;

        if (tid == 0) sCnt = 0;
        __syncthreads();

        int f = base + tid;
        if (f < nF) {
            float4 bb = g_BB2[f];
            float zmn = g_zminS[f];
            bool ok = (bb.x <= txmax) && (bb.z >= txmin) &&
                      (bb.y <= tymax) && (bb.w >= tymin) &&
                      (zmn <= zCap);
            if (ok) {
                float4 fa = g_FA2[f];
                float4 fb = g_FB2[f];
                float4 fc = g_FC2[f];
                float u0c = fmaf(fa.x, tcx, fmaf(fa.y, tcy, fa.z));
                float m0  = fmaf(fabsf(fa.x), thx, fmaf(fabsf(fa.y), thy, u0c));
                float u1c = fmaf(fa.w, tcx, fmaf(fb.x, tcy, fb.y));
                float m1  = fmaf(fabsf(fa.w), thx, fmaf(fabsf(fb.x), thy, u1c));
                float u2c = fmaf(fb.z, tcx, fmaf(fb.w, tcy, fc.x));
                float m2  = fmaf(fabsf(fb.z), thx, fmaf(fabsf(fb.w), thy, u2c));
                bool keep = (m0 >= -1e-5f * fmaxf(1.0f, fabsf(u0c))) &&
                            (m1 >= -1e-5f * fmaxf(1.0f, fabsf(u1c))) &&
                            (m2 >= -1e-5f * fmaxf(1.0f, fabsf(u2c)));
                if (keep) {
                    int p = atomicAdd(&sCnt, 1);
                    sIdx[p] = g_idx2[f];
                    sZm[p]  = zmn;
                    sA[p]   = fa;
                    sB[p]   = fb;
                    sC[p]   = fc;
                }
            }
        }
        __syncthreads();
        int cnt = sCnt;

        // warp-wide upper bound on zbest (32 pixels)
        float w = zb0;
        #pragma unroll
        for (int off = 16; off > 0; off >>= 1)
            w = fmaxf(w, __shfl_xor_sync(0xffffffffu, w, off));

        for (int i = 0; i < cnt; i++) {
            if ((i & 63) == 63) {
                float wr = zb0;
                #pragma unroll
                for (int off = 16; off > 0; off >>= 1)
                    wr = fmaxf(wr, __shfl_xor_sync(0xffffffffu, wr, off));
                w = wr;
            }
            if (sZm[i] > w) continue;
            float4 fa = sA[i];
            float4 fb = sB[i];
            float4 fc = sC[i];
            int    fi = sIdx[i];
            float u0 = fmaf(fa.x, px, fmaf(fa.y, py, fa.z));
            float u1 = fmaf(fa.w, px, fmaf(fb.x, py, fb.y));
            float u2 = fmaf(fb.z, px, fmaf(fb.w, py, fc.x));
            float z  = fmaf(fc.y, px, fmaf(fc.z, py, fc.w));
            float mm = fminf(u0, fminf(u1, u2));
            if (mm >= 0.0f && z > NEARP &&
                (z < zb0 || (z == zb0 && fi < b0))) {
                zb0 = z; b0 = fi;
            }
        }

        // refresh block-wide max zbest for the break test
        float m = zb0;
        #pragma unroll
        for (int off = 16; off > 0; off >>= 1)
            m = fmaxf(m, __shfl_xor_sync(0xffffffffu, m, off));
        if ((tid & 31) == 0) sWmax[wid] = m;
        __syncthreads();
        if (tid == 0) {
            float bm = sWmax[0];
            #pragma unroll
            for (int k = 1; k < 8; k++) bm = fmaxf(bm, sWmax[k]);
            sBmax = bm;
        }
        __syncthreads();
    }

    float loss;
    {
        float r = 0.f, g = 0.f, b = 0.f;
        if (b0 >= 0) { float4 c = g_COL[b0]; r = c.x; g = c.y; b = c.z; }
        int ry = HH - 1 - y;
        float d0 = r - image_ref[0*HH*WW + ry*WW + x];
        float d1 = g - image_ref[1*HH*WW + ry*WW + x];
        float d2 = b - image_ref[2*HH*WW + ry*WW + x];
        loss = d0*d0 + d1*d1 + d2*d2;
    }

    __syncthreads();
    sRed[tid] = loss;
    __syncthreads();
    #pragma unroll
    for (int s = 128; s > 0; s >>= 1) {
        if (tid < s) sRed[tid] += sRed[tid + s];
        __syncthreads();
    }
    if (tid == 0) {
        g_partials[bid] = sRed[0];
        __threadfence();
        int prev = atomicAdd(&g_done, 1);
        sIsLast = (prev == NBLK - 1) ? 1 : 0;
    }
    __syncthreads();

    if (sIsLast) {
        volatile float* vp = (volatile float*)g_partials;
        float s = 0.f;
        #pragma unroll
        for (int k = 0; k < NBLK / 256; k++) s += vp[tid + k * 256];
        sRed[tid] = s;
        __syncthreads();
        #pragma unroll
        for (int st = 128; st > 0; st >>= 1) {
            if (tid < st) sRed[tid] += sRed[tid + st];
            __syncthreads();
        }
        if (tid == 0) out[0] = sRed[0];
    }
}

// ---------------- entry point ----------------
extern "C" void kernel_launch(void* const* d_in, const int* in_sizes, int n_in,
                              void* d_out, int out_size) {
    const float* v         = (const float*)d_in[0];   // (1, V, 3)
    const int*   faces     = (const int*)  d_in[1];   // (1, F, 3)
    const float* tex       = (const float*)d_in[2];   // (1, F, 2,2,2,3)
    const float* campos    = (const float*)d_in[3];   // (3,)
    const float* camup     = (const float*)d_in[4];   // (3,)
    const float* image_ref = (const float*)d_in[5];   // (1, 3, H, W)

    int nV = in_sizes[0] / 3;
    int nF = in_sizes[1] / 3;

    k_verts<<<(nV + 255) / 256, 256>>>(v, campos, camup, nV);
    k_faces<<<(nF + 255) / 256, 256>>>(faces, tex, nF);
    k_scatter<<<(nF + 1023) / 1024, 1024>>>(nF);
    k_render<<<dim3(NBX, NBY), dim3(16, 16)>>>(image_ref, nF, (float*)d_out);
}